// round 8
// baseline (speedup 1.0000x reference)
#include <cuda_runtime.h>

// Fused SSIM loss. pred/target: [32,1,512,512] f32, WIN=11 VALID -> 502x502.
// out[0] = 1 - mean(S).
//
// R6: algebraic reduction 5 -> 4 box filters. SSIM only needs vx+vy, so
// Sxx and Syy fuse into one filter S(x^2+y^2):
//   B2 = (Sxx+Syy)/120 - cn*(ux^2+uy^2) + C2.
// Cuts smem staging and horizontal sliding by 20%, frees registers ->
// (128,8) launch bounds for ~41% occupancy on top of R5's prefetch pipeline.

#define BATCH   32
#define HH      512
#define WW      512
#define WIN     11
#define OHH     502
#define OWW     502
#define NBANDS  32
#define RPB     16
#define TPB     128
#define NBLK    (BATCH * NBANDS)   // 1024

__device__ float        g_partial[NBLK];
__device__ unsigned int g_count = 0;

__global__ __launch_bounds__(TPB, 8) void ssim_main(const float* __restrict__ pred,
                                                    const float* __restrict__ targ,
                                                    float* __restrict__ out)
{
    const int band = blockIdx.x;
    const int img  = blockIdx.y;
    const int r0   = band * RPB;
    int rend = r0 + RPB - 1;
    if (rend > OHH - 1) rend = OHH - 1;

    const int t = threadIdx.x;          // 0..127
    const int c = t << 2;               // 4 cols per thread, c in [0,508]

    // Double-buffered staging of 4 vertical-sum rows; float4 index = thread id.
    // Loads at t+1..t+3 are consecutive -> conflict-free. Pad 128..131 zeroed.
    __shared__ float4 sv[2][4][132];
    __shared__ float  wsum[4];
    __shared__ int    is_last;
    __shared__ double dred[TPB];

    {
        const float4 z4 = make_float4(0.f, 0.f, 0.f, 0.f);
        if (t < 32) {                   // 2 buf * 4 q * 4 pad entries
            int b = t / 16, rem = t % 16;
            sv[b][rem / 4][128 + (rem & 3)] = z4;
        }
    }

    const float* pb = pred + img * (HH * WW);
    const float* qb = targ + img * (HH * WW);

    // Vertical sliding sums: s0=Sx, s1=Sy, s2=S(x^2+y^2), s3=Sxy.
    float s[4][4];
#pragma unroll
    for (int q = 0; q < 4; ++q)
#pragma unroll
        for (int j = 0; j < 4; ++j) s[q][j] = 0.f;

    // Warm-up: rows r0 .. r0+9.
    for (int rr = r0; rr < r0 + WIN - 1; ++rr) {
        const float4 p4 = *(const float4*)(pb + rr * WW + c);
        const float4 q4 = *(const float4*)(qb + rr * WW + c);
        const float pj[4] = {p4.x, p4.y, p4.z, p4.w};
        const float qj[4] = {q4.x, q4.y, q4.z, q4.w};
#pragma unroll
        for (int j = 0; j < 4; ++j) {
            s[0][j] += pj[j];
            s[1][j] += qj[j];
            s[2][j] = fmaf(pj[j], pj[j], fmaf(qj[j], qj[j], s[2][j]));
            s[3][j] = fmaf(pj[j], qj[j], s[3][j]);
        }
    }

    const float inv_np = 1.0f / 121.0f;
    const float k120   = 1.0f / 120.0f;     // cov_norm / NP
    const float cn     = 121.0f / 120.0f;   // cov_norm
    const float C1     = 1.0e-4f;
    const float C2     = 9.0e-4f;

    float acc = 0.0f;

    // Pipeline prologue: preload bottom row for the first iteration.
    float4 pn = *(const float4*)(pb + (r0 + WIN - 1) * WW + c);
    float4 qn = *(const float4*)(qb + (r0 + WIN - 1) * WW + c);

    for (int orow = r0; orow <= rend; ++orow) {
        const int par = orow & 1;

        // Old top row (consumed at the end of this iteration -> latency hidden).
        const float4 po = *(const float4*)(pb + orow * WW + c);
        const float4 qo = *(const float4*)(qb + orow * WW + c);

        {   // add prefetched new row -> sums cover rows orow..orow+10
            const float pj[4] = {pn.x, pn.y, pn.z, pn.w};
            const float qj[4] = {qn.x, qn.y, qn.z, qn.w};
#pragma unroll
            for (int j = 0; j < 4; ++j) {
                s[0][j] += pj[j];
                s[1][j] += qj[j];
                s[2][j] = fmaf(pj[j], pj[j], fmaf(qj[j], qj[j], s[2][j]));
                s[3][j] = fmaf(qj[j], pj[j], s[3][j]);
            }
        }

        // Stage vertical sums.
#pragma unroll
        for (int q = 0; q < 4; ++q)
            sv[par][q][t] = make_float4(s[q][0], s[q][1], s[q][2], s[q][3]);

        // Prefetch next iteration's bottom row NOW (clamped; covered by
        // barrier + horizontal + SSIM below).
        {
            int rnext = orow + WIN;                 // (orow+1) + 10
            if (rnext > HH - 1) rnext = HH - 1;
            pn = *(const float4*)(pb + rnext * WW + c);
            qn = *(const float4*)(qb + rnext * WW + c);
        }

        __syncthreads();

        // Horizontal 11-window sums, streamed: compute w[q] for col c, do
        // SSIM, slide. Slide-in scalars cached; halo from smem.
        float w[4];
        float si1[4], si2[4], si3[4];
#pragma unroll
        for (int q = 0; q < 4; ++q) {
            const float4 n0 = sv[par][q][t + 1];
            const float4 n1 = sv[par][q][t + 2];
            const float4 n2 = sv[par][q][t + 3];
            w[q] = s[q][0] + s[q][1] + s[q][2] + s[q][3]
                 + n0.x + n0.y + n0.z + n0.w
                 + n1.x + n1.y + n1.z;              // cols c..c+10
            si1[q] = n1.w; si2[q] = n2.x; si3[q] = n2.y;
        }

#pragma unroll
        for (int j = 0; j < 4; ++j) {
            if (j) {
                const float* si = (j == 1) ? si1 : (j == 2) ? si2 : si3;
#pragma unroll
                for (int q = 0; q < 4; ++q)
                    w[q] = w[q] - s[q][j - 1] + si[q];
            }
            const float ux  = w[0] * inv_np;
            const float uy  = w[1] * inv_np;
            const float uxy = ux * uy;
            const float sq  = fmaf(ux, ux, uy * uy);
            const float A1  = fmaf(2.0f, uxy, C1);
            const float B1  = sq + C1;
            const float vxy = fmaf(w[3], k120, -cn * uxy);
            const float vs  = fmaf(w[2], k120, -cn * sq);   // vx + vy
            const float A2  = fmaf(2.0f, vxy, C2);
            const float B2  = vs + C2;
            const float S   = __fdividef(A1 * A2, B1 * B2);
            if (c + j < OWW) acc += S;
        }

        {   // subtract old top row -> sums cover orow+1..orow+10
            const float pj[4] = {po.x, po.y, po.z, po.w};
            const float qj[4] = {qo.x, qo.y, qo.z, qo.w};
#pragma unroll
            for (int j = 0; j < 4; ++j) {
                s[0][j] -= pj[j];
                s[1][j] -= qj[j];
                s[2][j] = fmaf(-pj[j], pj[j], fmaf(-qj[j], qj[j], s[2][j]));
                s[3][j] = fmaf(-qj[j], pj[j], s[3][j]);
            }
        }
    }

    // Block reduction (4 warps).
    float v = acc;
#pragma unroll
    for (int off = 16; off; off >>= 1)
        v += __shfl_xor_sync(0xffffffffu, v, off);
    const int lane = t & 31, wid = t >> 5;
    if (lane == 0) wsum[wid] = v;
    __syncthreads();

    if (t == 0) {
        g_partial[img * NBANDS + band] = wsum[0] + wsum[1] + wsum[2] + wsum[3];
        __threadfence();
        const unsigned int tick = atomicAdd(&g_count, 1u);
        is_last = (tick == NBLK - 1);
    }
    __syncthreads();

    // Last block performs the deterministic final reduction.
    if (is_last) {
        __threadfence();
        double sd = 0.0;
        for (int i = t; i < NBLK; i += TPB)   // fixed slots, fixed order
            sd += (double)g_partial[i];
        dred[t] = sd;
        __syncthreads();
#pragma unroll
        for (int st = TPB / 2; st > 0; st >>= 1) {
            if (t < st) dred[t] += dred[t + st];
            __syncthreads();
        }
        if (t == 0) {
            out[0] = (float)(1.0 - dred[0] / ((double)BATCH * OHH * OWW));
            g_count = 0;   // reset for next graph replay
        }
    }
}

extern "C" void kernel_launch(void* const* d_in, const int* in_sizes, int n_in,
                              void* d_out, int out_size)
{
    const float* pred = (const float*)d_in[0];
    const float* targ = (const float*)d_in[1];
    float* out = (float*)d_out;

    ssim_main<<<dim3(NBANDS, BATCH), TPB>>>(pred, targ, out);
}

// round 9
// speedup vs baseline: 1.2929x; 1.2929x over previous
#include <cuda_runtime.h>

// Fused SSIM loss. pred/target: [32,1,512,512] f32, WIN=11 VALID -> 502x502.
// out[0] = 1 - mean(S).
//
// R7 = R6 algebra (4 box filters: Sx, Sy, S(x^2+y^2), Sxy) + R5 launch bounds
// (128,7). R6's forced (128,8) hit the 64-reg ceiling and spilled (alu 4.8->8.7%,
// timed 45us); occupancy beyond ~36% was already shown useless, so let the
// compiler have its ~70 regs.

#define BATCH   32
#define HH      512
#define WW      512
#define WIN     11
#define OHH     502
#define OWW     502
#define NBANDS  32
#define RPB     16
#define TPB     128
#define NBLK    (BATCH * NBANDS)   // 1024

__device__ float        g_partial[NBLK];
__device__ unsigned int g_count = 0;

__global__ __launch_bounds__(TPB, 7) void ssim_main(const float* __restrict__ pred,
                                                    const float* __restrict__ targ,
                                                    float* __restrict__ out)
{
    const int band = blockIdx.x;
    const int img  = blockIdx.y;
    const int r0   = band * RPB;
    int rend = r0 + RPB - 1;
    if (rend > OHH - 1) rend = OHH - 1;

    const int t = threadIdx.x;          // 0..127
    const int c = t << 2;               // 4 cols per thread, c in [0,508]

    // Double-buffered staging of 4 vertical-sum rows; float4 index = thread id.
    // Loads at t+1..t+3 are consecutive -> conflict-free. Pad 128..131 zeroed.
    __shared__ float4 sv[2][4][132];
    __shared__ float  wsum[4];
    __shared__ int    is_last;
    __shared__ double dred[TPB];

    {
        const float4 z4 = make_float4(0.f, 0.f, 0.f, 0.f);
        if (t < 32) {                   // 2 buf * 4 q * 4 pad entries
            int b = t / 16, rem = t % 16;
            sv[b][rem / 4][128 + (rem & 3)] = z4;
        }
    }

    const float* pb = pred + img * (HH * WW);
    const float* qb = targ + img * (HH * WW);

    // Vertical sliding sums: s0=Sx, s1=Sy, s2=S(x^2+y^2), s3=Sxy.
    float s[4][4];
#pragma unroll
    for (int q = 0; q < 4; ++q)
#pragma unroll
        for (int j = 0; j < 4; ++j) s[q][j] = 0.f;

    // Warm-up: rows r0 .. r0+9.
    for (int rr = r0; rr < r0 + WIN - 1; ++rr) {
        const float4 p4 = *(const float4*)(pb + rr * WW + c);
        const float4 q4 = *(const float4*)(qb + rr * WW + c);
        const float pj[4] = {p4.x, p4.y, p4.z, p4.w};
        const float qj[4] = {q4.x, q4.y, q4.z, q4.w};
#pragma unroll
        for (int j = 0; j < 4; ++j) {
            s[0][j] += pj[j];
            s[1][j] += qj[j];
            s[2][j] = fmaf(pj[j], pj[j], fmaf(qj[j], qj[j], s[2][j]));
            s[3][j] = fmaf(pj[j], qj[j], s[3][j]);
        }
    }

    const float inv_np = 1.0f / 121.0f;
    const float k120   = 1.0f / 120.0f;     // cov_norm / NP
    const float cn     = 121.0f / 120.0f;   // cov_norm
    const float C1     = 1.0e-4f;
    const float C2     = 9.0e-4f;

    float acc = 0.0f;

    // Pipeline prologue: preload bottom row for the first iteration.
    float4 pn = *(const float4*)(pb + (r0 + WIN - 1) * WW + c);
    float4 qn = *(const float4*)(qb + (r0 + WIN - 1) * WW + c);

    for (int orow = r0; orow <= rend; ++orow) {
        const int par = orow & 1;

        // Old top row (consumed at the end of this iteration -> latency hidden).
        const float4 po = *(const float4*)(pb + orow * WW + c);
        const float4 qo = *(const float4*)(qb + orow * WW + c);

        {   // add prefetched new row -> sums cover rows orow..orow+10
            const float pj[4] = {pn.x, pn.y, pn.z, pn.w};
            const float qj[4] = {qn.x, qn.y, qn.z, qn.w};
#pragma unroll
            for (int j = 0; j < 4; ++j) {
                s[0][j] += pj[j];
                s[1][j] += qj[j];
                s[2][j] = fmaf(pj[j], pj[j], fmaf(qj[j], qj[j], s[2][j]));
                s[3][j] = fmaf(qj[j], pj[j], s[3][j]);
            }
        }

        // Stage vertical sums.
#pragma unroll
        for (int q = 0; q < 4; ++q)
            sv[par][q][t] = make_float4(s[q][0], s[q][1], s[q][2], s[q][3]);

        // Prefetch next iteration's bottom row NOW (clamped; covered by
        // barrier + horizontal + SSIM below).
        {
            int rnext = orow + WIN;                 // (orow+1) + 10
            if (rnext > HH - 1) rnext = HH - 1;
            pn = *(const float4*)(pb + rnext * WW + c);
            qn = *(const float4*)(qb + rnext * WW + c);
        }

        __syncthreads();

        // Horizontal 11-window sums, streamed: compute w[q] for col c, do
        // SSIM, slide. Slide-in scalars cached; halo from smem.
        float w[4];
        float si1[4], si2[4], si3[4];
#pragma unroll
        for (int q = 0; q < 4; ++q) {
            const float4 n0 = sv[par][q][t + 1];
            const float4 n1 = sv[par][q][t + 2];
            const float4 n2 = sv[par][q][t + 3];
            w[q] = s[q][0] + s[q][1] + s[q][2] + s[q][3]
                 + n0.x + n0.y + n0.z + n0.w
                 + n1.x + n1.y + n1.z;              // cols c..c+10
            si1[q] = n1.w; si2[q] = n2.x; si3[q] = n2.y;
        }

#pragma unroll
        for (int j = 0; j < 4; ++j) {
            if (j) {
                const float* si = (j == 1) ? si1 : (j == 2) ? si2 : si3;
#pragma unroll
                for (int q = 0; q < 4; ++q)
                    w[q] = w[q] - s[q][j - 1] + si[q];
            }
            const float ux  = w[0] * inv_np;
            const float uy  = w[1] * inv_np;
            const float uxy = ux * uy;
            const float sq  = fmaf(ux, ux, uy * uy);
            const float A1  = fmaf(2.0f, uxy, C1);
            const float B1  = sq + C1;
            const float vxy = fmaf(w[3], k120, -cn * uxy);
            const float vs  = fmaf(w[2], k120, -cn * sq);   // vx + vy
            const float A2  = fmaf(2.0f, vxy, C2);
            const float B2  = vs + C2;
            const float S   = __fdividef(A1 * A2, B1 * B2);
            if (c + j < OWW) acc += S;
        }

        {   // subtract old top row -> sums cover orow+1..orow+10
            const float pj[4] = {po.x, po.y, po.z, po.w};
            const float qj[4] = {qo.x, qo.y, qo.z, qo.w};
#pragma unroll
            for (int j = 0; j < 4; ++j) {
                s[0][j] -= pj[j];
                s[1][j] -= qj[j];
                s[2][j] = fmaf(-pj[j], pj[j], fmaf(-qj[j], qj[j], s[2][j]));
                s[3][j] = fmaf(-qj[j], pj[j], s[3][j]);
            }
        }
    }

    // Block reduction (4 warps).
    float v = acc;
#pragma unroll
    for (int off = 16; off; off >>= 1)
        v += __shfl_xor_sync(0xffffffffu, v, off);
    const int lane = t & 31, wid = t >> 5;
    if (lane == 0) wsum[wid] = v;
    __syncthreads();

    if (t == 0) {
        g_partial[img * NBANDS + band] = wsum[0] + wsum[1] + wsum[2] + wsum[3];
        __threadfence();
        const unsigned int tick = atomicAdd(&g_count, 1u);
        is_last = (tick == NBLK - 1);
    }
    __syncthreads();

    // Last block performs the deterministic final reduction.
    if (is_last) {
        __threadfence();
        double sd = 0.0;
        for (int i = t; i < NBLK; i += TPB)   // fixed slots, fixed order
            sd += (double)g_partial[i];
        dred[t] = sd;
        __syncthreads();
#pragma unroll
        for (int st = TPB / 2; st > 0; st >>= 1) {
            if (t < st) dred[t] += dred[t + st];
            __syncthreads();
        }
        if (t == 0) {
            out[0] = (float)(1.0 - dred[0] / ((double)BATCH * OHH * OWW));
            g_count = 0;   // reset for next graph replay
        }
    }
}

extern "C" void kernel_launch(void* const* d_in, const int* in_sizes, int n_in,
                              void* d_out, int out_size)
{
    const float* pred = (const float*)d_in[0];
    const float* targ = (const float*)d_in[1];
    float* out = (float*)d_out;

    ssim_main<<<dim3(NBANDS, BATCH), TPB>>>(pred, targ, out);
}

// round 10
// speedup vs baseline: 1.4194x; 1.0978x over previous
#include <cuda_runtime.h>

// Fused SSIM loss. pred/target: [32,1,512,512] f32, WIN=11 VALID -> 502x502.
// out[0] = 1 - mean(S).
//
// R8 = R7 (4 box filters, depth-1 prefetch) with the bottom-row prefetch
// deepened to distance 2 (pn2/qn2). R7 showed the kernel is latency-bound:
// cutting 15% of instructions moved time <1%. The remaining exposure is L2
// latency variance on the pre-barrier row loads; depth-2 gives ~2 iterations
// (~600 cyc) of slack. (128,6) bounds for the +8 regs; 896-block single wave.

#define BATCH   32
#define HH      512
#define WW      512
#define WIN     11
#define OHH     502
#define OWW     502
#define NBANDS  28
#define RPB     18
#define TPB     128
#define NBLK    (BATCH * NBANDS)   // 896

__device__ float        g_partial[NBLK];
__device__ unsigned int g_count = 0;

__global__ __launch_bounds__(TPB, 6) void ssim_main(const float* __restrict__ pred,
                                                    const float* __restrict__ targ,
                                                    float* __restrict__ out)
{
    const int band = blockIdx.x;
    const int img  = blockIdx.y;
    const int r0   = band * RPB;
    int rend = r0 + RPB - 1;
    if (rend > OHH - 1) rend = OHH - 1;

    const int t = threadIdx.x;          // 0..127
    const int c = t << 2;               // 4 cols per thread, c in [0,508]

    // Double-buffered staging of 4 vertical-sum rows; float4 index = thread id.
    // Loads at t+1..t+3 are consecutive -> conflict-free. Pad 128..131 zeroed.
    __shared__ float4 sv[2][4][132];
    __shared__ float  wsum[4];
    __shared__ int    is_last;
    __shared__ double dred[TPB];

    {
        const float4 z4 = make_float4(0.f, 0.f, 0.f, 0.f);
        if (t < 32) {                   // 2 buf * 4 q * 4 pad entries
            int b = t / 16, rem = t % 16;
            sv[b][rem / 4][128 + (rem & 3)] = z4;
        }
    }

    const float* pb = pred + img * (HH * WW);
    const float* qb = targ + img * (HH * WW);

    // Vertical sliding sums: s0=Sx, s1=Sy, s2=S(x^2+y^2), s3=Sxy.
    float s[4][4];
#pragma unroll
    for (int q = 0; q < 4; ++q)
#pragma unroll
        for (int j = 0; j < 4; ++j) s[q][j] = 0.f;

    // Warm-up: rows r0 .. r0+9.
    for (int rr = r0; rr < r0 + WIN - 1; ++rr) {
        const float4 p4 = *(const float4*)(pb + rr * WW + c);
        const float4 q4 = *(const float4*)(qb + rr * WW + c);
        const float pj[4] = {p4.x, p4.y, p4.z, p4.w};
        const float qj[4] = {q4.x, q4.y, q4.z, q4.w};
#pragma unroll
        for (int j = 0; j < 4; ++j) {
            s[0][j] += pj[j];
            s[1][j] += qj[j];
            s[2][j] = fmaf(pj[j], pj[j], fmaf(qj[j], qj[j], s[2][j]));
            s[3][j] = fmaf(pj[j], qj[j], s[3][j]);
        }
    }

    const float inv_np = 1.0f / 121.0f;
    const float k120   = 1.0f / 120.0f;     // cov_norm / NP
    const float cn     = 121.0f / 120.0f;   // cov_norm
    const float C1     = 1.0e-4f;
    const float C2     = 9.0e-4f;

    float acc = 0.0f;

    // Depth-2 pipeline prologue: rows r0+10 and r0+11 in flight.
    float4 pn  = *(const float4*)(pb + (r0 + WIN - 1) * WW + c);
    float4 qn  = *(const float4*)(qb + (r0 + WIN - 1) * WW + c);
    float4 pn2 = *(const float4*)(pb + (r0 + WIN) * WW + c);
    float4 qn2 = *(const float4*)(qb + (r0 + WIN) * WW + c);

    for (int orow = r0; orow <= rend; ++orow) {
        const int par = orow & 1;

        // Old top row (consumed at the end of this iteration -> latency hidden).
        const float4 po = *(const float4*)(pb + orow * WW + c);
        const float4 qo = *(const float4*)(qb + orow * WW + c);

        {   // add prefetched new row -> sums cover rows orow..orow+10
            const float pj[4] = {pn.x, pn.y, pn.z, pn.w};
            const float qj[4] = {qn.x, qn.y, qn.z, qn.w};
#pragma unroll
            for (int j = 0; j < 4; ++j) {
                s[0][j] += pj[j];
                s[1][j] += qj[j];
                s[2][j] = fmaf(pj[j], pj[j], fmaf(qj[j], qj[j], s[2][j]));
                s[3][j] = fmaf(qj[j], pj[j], s[3][j]);
            }
        }

        // Stage vertical sums.
#pragma unroll
        for (int q = 0; q < 4; ++q)
            sv[par][q][t] = make_float4(s[q][0], s[q][1], s[q][2], s[q][3]);

        // Rotate pipeline, then issue the distance-2 load (row orow+12,
        // consumed two iterations from now; clamped, over-reads unused).
        pn = pn2; qn = qn2;
        {
            int rnext2 = orow + WIN + 1;
            if (rnext2 > HH - 1) rnext2 = HH - 1;
            pn2 = *(const float4*)(pb + rnext2 * WW + c);
            qn2 = *(const float4*)(qb + rnext2 * WW + c);
        }

        __syncthreads();

        // Horizontal 11-window sums, streamed: compute w[q] for col c, do
        // SSIM, slide. Slide-in scalars cached; halo from smem.
        float w[4];
        float si1[4], si2[4], si3[4];
#pragma unroll
        for (int q = 0; q < 4; ++q) {
            const float4 n0 = sv[par][q][t + 1];
            const float4 n1 = sv[par][q][t + 2];
            const float4 n2 = sv[par][q][t + 3];
            w[q] = s[q][0] + s[q][1] + s[q][2] + s[q][3]
                 + n0.x + n0.y + n0.z + n0.w
                 + n1.x + n1.y + n1.z;              // cols c..c+10
            si1[q] = n1.w; si2[q] = n2.x; si3[q] = n2.y;
        }

#pragma unroll
        for (int j = 0; j < 4; ++j) {
            if (j) {
                const float* si = (j == 1) ? si1 : (j == 2) ? si2 : si3;
#pragma unroll
                for (int q = 0; q < 4; ++q)
                    w[q] = w[q] - s[q][j - 1] + si[q];
            }
            const float ux  = w[0] * inv_np;
            const float uy  = w[1] * inv_np;
            const float uxy = ux * uy;
            const float sq  = fmaf(ux, ux, uy * uy);
            const float A1  = fmaf(2.0f, uxy, C1);
            const float B1  = sq + C1;
            const float vxy = fmaf(w[3], k120, -cn * uxy);
            const float vs  = fmaf(w[2], k120, -cn * sq);   // vx + vy
            const float A2  = fmaf(2.0f, vxy, C2);
            const float B2  = vs + C2;
            const float S   = __fdividef(A1 * A2, B1 * B2);
            if (c + j < OWW) acc += S;
        }

        {   // subtract old top row -> sums cover orow+1..orow+10
            const float pj[4] = {po.x, po.y, po.z, po.w};
            const float qj[4] = {qo.x, qo.y, qo.z, qo.w};
#pragma unroll
            for (int j = 0; j < 4; ++j) {
                s[0][j] -= pj[j];
                s[1][j] -= qj[j];
                s[2][j] = fmaf(-pj[j], pj[j], fmaf(-qj[j], qj[j], s[2][j]));
                s[3][j] = fmaf(-qj[j], pj[j], s[3][j]);
            }
        }
    }

    // Block reduction (4 warps).
    float v = acc;
#pragma unroll
    for (int off = 16; off; off >>= 1)
        v += __shfl_xor_sync(0xffffffffu, v, off);
    const int lane = t & 31, wid = t >> 5;
    if (lane == 0) wsum[wid] = v;
    __syncthreads();

    if (t == 0) {
        g_partial[img * NBANDS + band] = wsum[0] + wsum[1] + wsum[2] + wsum[3];
        __threadfence();
        const unsigned int tick = atomicAdd(&g_count, 1u);
        is_last = (tick == NBLK - 1);
    }
    __syncthreads();

    // Last block performs the deterministic final reduction.
    if (is_last) {
        __threadfence();
        double sd = 0.0;
        for (int i = t; i < NBLK; i += TPB)   // fixed slots, fixed order
            sd += (double)g_partial[i];
        dred[t] = sd;
        __syncthreads();
#pragma unroll
        for (int st = TPB / 2; st > 0; st >>= 1) {
            if (t < st) dred[t] += dred[t + st];
            __syncthreads();
        }
        if (t == 0) {
            out[0] = (float)(1.0 - dred[0] / ((double)BATCH * OHH * OWW));
            g_count = 0;   // reset for next graph replay
        }
    }
}

extern "C" void kernel_launch(void* const* d_in, const int* in_sizes, int n_in,
                              void* d_out, int out_size)
{
    const float* pred = (const float*)d_in[0];
    const float* targ = (const float*)d_in[1];
    float* out = (float*)d_out;

    ssim_main<<<dim3(NBANDS, BATCH), TPB>>>(pred, targ, out);
}

// round 12
// speedup vs baseline: 1.4426x; 1.0164x over previous
#include <cuda_runtime.h>

// Fused SSIM loss. pred/target: [32,1,512,512] f32, WIN=11 VALID -> 502x502.
// out[0] = 1 - mean(S).
//
// R9 = R8 + two output rows per __syncthreads (4 staging buffer sets, one
// barrier per row-PAIR), single clean wave of 736 blocks at 5 blocks/SM.
// R7/R8 established the kernel is latency+lockstep bound; this halves the
// lockstep points and per-row loop overhead.

#define BATCH   32
#define HH      512
#define WW      512
#define WIN     11
#define OHH     502
#define OWW     502
#define NBANDS  23
#define RPB     22
#define TPB     128
#define NBLK    (BATCH * NBANDS)   // 736

__device__ float        g_partial[NBLK];
__device__ unsigned int g_count = 0;

__global__ __launch_bounds__(TPB, 5) void ssim_main(const float* __restrict__ pred,
                                                    const float* __restrict__ targ,
                                                    float* __restrict__ out)
{
    const int band = blockIdx.x;
    const int img  = blockIdx.y;
    const int r0   = band * RPB;
    int rend = r0 + RPB - 1;
    if (rend > OHH - 1) rend = OHH - 1;   // band 22: rows 484..501 (18 rows)

    const int t = threadIdx.x;          // 0..127
    const int c = t << 2;               // 4 cols per thread, c in [0,508]

    // 4 staging buffer sets: [pair parity][row-in-pair][quantity][float4 idx].
    // Neighbor loads at t+1..t+3 are consecutive -> conflict-free.
    __shared__ float4 sv[2][2][4][132];
    __shared__ float  wsum[4];
    __shared__ int    is_last;
    __shared__ double dred[TPB];

    {   // zero pads (idx 128..131) of all 16 q-buffers
        const float4 z4 = make_float4(0.f, 0.f, 0.f, 0.f);
        if (t < 64) {
            int pp = t >> 5, rb = (t >> 4) & 1, q = (t >> 2) & 3, k = t & 3;
            sv[pp][rb][q][128 + k] = z4;
        }
    }

    const float* pb = pred + img * (HH * WW);
    const float* qb = targ + img * (HH * WW);

    // Vertical sliding sums: s0=Sx, s1=Sy, s2=S(x^2+y^2), s3=Sxy.
    float s[4][4];
#pragma unroll
    for (int q = 0; q < 4; ++q)
#pragma unroll
        for (int j = 0; j < 4; ++j) s[q][j] = 0.f;

    // Warm-up: rows r0 .. r0+9.
    for (int rr = r0; rr < r0 + WIN - 1; ++rr) {
        const float4 p4 = *(const float4*)(pb + rr * WW + c);
        const float4 q4 = *(const float4*)(qb + rr * WW + c);
        const float pj[4] = {p4.x, p4.y, p4.z, p4.w};
        const float qj[4] = {q4.x, q4.y, q4.z, q4.w};
#pragma unroll
        for (int j = 0; j < 4; ++j) {
            s[0][j] += pj[j];
            s[1][j] += qj[j];
            s[2][j] = fmaf(pj[j], pj[j], fmaf(qj[j], qj[j], s[2][j]));
            s[3][j] = fmaf(pj[j], qj[j], s[3][j]);
        }
    }

    const float inv_np = 1.0f / 121.0f;
    const float k120   = 1.0f / 120.0f;     // cov_norm / NP
    const float cn     = 121.0f / 120.0f;   // cov_norm
    const float C1     = 1.0e-4f;
    const float C2     = 9.0e-4f;

    float acc = 0.0f;

    // Prefetch the first new-row pair (rows r0+10, r0+11).
    float4 pA = *(const float4*)(pb + (r0 + WIN - 1) * WW + c);
    float4 qA = *(const float4*)(qb + (r0 + WIN - 1) * WW + c);
    float4 pB = *(const float4*)(pb + (r0 + WIN) * WW + c);
    float4 qB = *(const float4*)(qb + (r0 + WIN) * WW + c);

    for (int orow = r0; orow <= rend; orow += 2) {
        const int pp = ((orow - r0) >> 1) & 1;

        // Old top rows (orow, orow+1).
        const float4 po0 = *(const float4*)(pb + orow * WW + c);
        const float4 qo0 = *(const float4*)(qb + orow * WW + c);
        const float4 po1 = *(const float4*)(pb + (orow + 1) * WW + c);
        const float4 qo1 = *(const float4*)(qb + (orow + 1) * WW + c);

        {   // add row orow+10 -> s covers rows orow..orow+10
            const float pj[4] = {pA.x, pA.y, pA.z, pA.w};
            const float qj[4] = {qA.x, qA.y, qA.z, qA.w};
#pragma unroll
            for (int j = 0; j < 4; ++j) {
                s[0][j] += pj[j];
                s[1][j] += qj[j];
                s[2][j] = fmaf(pj[j], pj[j], fmaf(qj[j], qj[j], s[2][j]));
                s[3][j] = fmaf(qj[j], pj[j], s[3][j]);
            }
        }
#pragma unroll
        for (int q = 0; q < 4; ++q)
            sv[pp][0][q][t] = make_float4(s[q][0], s[q][1], s[q][2], s[q][3]);

        // Snapshot row-0 sums before advancing to row 1.
        float sOld[4][4];
#pragma unroll
        for (int q = 0; q < 4; ++q)
#pragma unroll
            for (int j = 0; j < 4; ++j) sOld[q][j] = s[q][j];

        {   // add row orow+11, sub row orow -> s covers orow+1..orow+11
            const float pj[4] = {pB.x, pB.y, pB.z, pB.w};
            const float qj[4] = {qB.x, qB.y, qB.z, qB.w};
            const float uj[4] = {po0.x, po0.y, po0.z, po0.w};
            const float vj[4] = {qo0.x, qo0.y, qo0.z, qo0.w};
#pragma unroll
            for (int j = 0; j < 4; ++j) {
                s[0][j] += pj[j] - uj[j];
                s[1][j] += qj[j] - vj[j];
                s[2][j] = fmaf(pj[j], pj[j], fmaf(qj[j], qj[j], s[2][j]));
                s[2][j] = fmaf(-uj[j], uj[j], fmaf(-vj[j], vj[j], s[2][j]));
                s[3][j] = fmaf(qj[j], pj[j], s[3][j]);
                s[3][j] = fmaf(-vj[j], uj[j], s[3][j]);
            }
        }
#pragma unroll
        for (int q = 0; q < 4; ++q)
            sv[pp][1][q][t] = make_float4(s[q][0], s[q][1], s[q][2], s[q][3]);

        // Prefetch next pair (rows orow+12, orow+13), clamped.
        {
            int rA = orow + WIN + 1; if (rA > HH - 1) rA = HH - 1;
            int rB = orow + WIN + 2; if (rB > HH - 1) rB = HH - 1;
            pA = *(const float4*)(pb + rA * WW + c);
            qA = *(const float4*)(qb + rA * WW + c);
            pB = *(const float4*)(pb + rB * WW + c);
            qB = *(const float4*)(qb + rB * WW + c);
        }

        __syncthreads();

        // Horizontal + SSIM for both rows of the pair.
#pragma unroll
        for (int rb = 0; rb < 2; ++rb) {
            const float (*sr)[4] = rb ? (const float (*)[4])s
                                      : (const float (*)[4])sOld;
            float w[4], si1[4], si2[4], si3[4];
#pragma unroll
            for (int q = 0; q < 4; ++q) {
                const float4 n0 = sv[pp][rb][q][t + 1];
                const float4 n1 = sv[pp][rb][q][t + 2];
                const float4 n2 = sv[pp][rb][q][t + 3];
                w[q] = sr[q][0] + sr[q][1] + sr[q][2] + sr[q][3]
                     + n0.x + n0.y + n0.z + n0.w
                     + n1.x + n1.y + n1.z;              // cols c..c+10
                si1[q] = n1.w; si2[q] = n2.x; si3[q] = n2.y;
            }
#pragma unroll
            for (int j = 0; j < 4; ++j) {
                if (j) {
                    const float* si = (j == 1) ? si1 : (j == 2) ? si2 : si3;
#pragma unroll
                    for (int q = 0; q < 4; ++q)
                        w[q] = w[q] - sr[q][j - 1] + si[q];
                }
                const float ux  = w[0] * inv_np;
                const float uy  = w[1] * inv_np;
                const float uxy = ux * uy;
                const float sq  = fmaf(ux, ux, uy * uy);
                const float A1  = fmaf(2.0f, uxy, C1);
                const float B1  = sq + C1;
                const float vxy = fmaf(w[3], k120, -cn * uxy);
                const float vs  = fmaf(w[2], k120, -cn * sq);   // vx + vy
                const float A2  = fmaf(2.0f, vxy, C2);
                const float B2  = vs + C2;
                const float S   = __fdividef(A1 * A2, B1 * B2);
                if (c + j < OWW) acc += S;
            }
        }

        {   // sub row orow+1 -> s covers orow+2..orow+11 for next pair
            const float uj[4] = {po1.x, po1.y, po1.z, po1.w};
            const float vj[4] = {qo1.x, qo1.y, qo1.z, qo1.w};
#pragma unroll
            for (int j = 0; j < 4; ++j) {
                s[0][j] -= uj[j];
                s[1][j] -= vj[j];
                s[2][j] = fmaf(-uj[j], uj[j], fmaf(-vj[j], vj[j], s[2][j]));
                s[3][j] = fmaf(-vj[j], uj[j], s[3][j]);
            }
        }
    }

    // Block reduction (4 warps).
    float v = acc;
#pragma unroll
    for (int off = 16; off; off >>= 1)
        v += __shfl_xor_sync(0xffffffffu, v, off);
    const int lane = t & 31, wid = t >> 5;
    if (lane == 0) wsum[wid] = v;
    __syncthreads();

    if (t == 0) {
        g_partial[img * NBANDS + band] = wsum[0] + wsum[1] + wsum[2] + wsum[3];
        __threadfence();
        const unsigned int tick = atomicAdd(&g_count, 1u);
        is_last = (tick == NBLK - 1);
    }
    __syncthreads();

    // Last block performs the deterministic final reduction.
    if (is_last) {
        __threadfence();
        double sd = 0.0;
        for (int i = t; i < NBLK; i += TPB)   // fixed slots, fixed order
            sd += (double)g_partial[i];
        dred[t] = sd;
        __syncthreads();
#pragma unroll
        for (int st = TPB / 2; st > 0; st >>= 1) {
            if (t < st) dred[t] += dred[t + st];
            __syncthreads();
        }
        if (t == 0) {
            out[0] = (float)(1.0 - dred[0] / ((double)BATCH * OHH * OWW));
            g_count = 0;   // reset for next graph replay
        }
    }
}

extern "C" void kernel_launch(void* const* d_in, const int* in_sizes, int n_in,
                              void* d_out, int out_size)
{
    const float* pred = (const float*)d_in[0];
    const float* targ = (const float*)d_in[1];
    float* out = (float*)d_out;

    ssim_main<<<dim3(NBANDS, BATCH), TPB>>>(pred, targ, out);
}